// round 1
// baseline (speedup 1.0000x reference)
#include <cuda_runtime.h>
#include <math.h>

#define BB 4
#define NN 2048
#define MM 2048
#define DM 512
#define HH 8
#define HD 64

// Scratch (allocation-free rule: __device__ globals)
__device__ float g_Q[BB * NN * DM];
__device__ float g_K[BB * MM * DM];
__device__ float g_V[BB * MM * DM];
__device__ float g_O[BB * NN * DM];
__device__ float g_Y[BB * NN * DM];

// ---------------------------------------------------------------------------
// GEMM body: C[R][512] = A[R][512] @ W[512][512]^T
// 64x64 block tile, K-tiles of 16, 256 threads, 4x4 microtile per thread.
// SMEM staged transposed (k-major) so compute reads are LDS.128 conflict-free.
// ---------------------------------------------------------------------------
__device__ __forceinline__ void gemm_body(const float* __restrict__ A,
                                          const float* __restrict__ W,
                                          float* __restrict__ C) {
    __shared__ float As[16][68];  // As[k][row]
    __shared__ float Ws[16][68];  // Ws[k][col]
    const int tid = threadIdx.x;
    const int tx = tid & 15;
    const int ty = tid >> 4;
    const int row0 = blockIdx.x * 64;
    const int col0 = blockIdx.y * 64;

    float acc[4][4];
#pragma unroll
    for (int i = 0; i < 4; i++)
#pragma unroll
        for (int j = 0; j < 4; j++) acc[i][j] = 0.f;

    const int lr = tid >> 2;          // 0..63
    const int lk = (tid & 3) << 2;    // 0,4,8,12
    const float* Ap = A + (size_t)(row0 + lr) * DM + lk;
    const float* Wp = W + (size_t)(col0 + lr) * DM + lk;

    for (int k0 = 0; k0 < DM; k0 += 16) {
        float4 av = *(const float4*)(Ap + k0);
        float4 wv = *(const float4*)(Wp + k0);
        As[lk + 0][lr] = av.x; As[lk + 1][lr] = av.y;
        As[lk + 2][lr] = av.z; As[lk + 3][lr] = av.w;
        Ws[lk + 0][lr] = wv.x; Ws[lk + 1][lr] = wv.y;
        Ws[lk + 2][lr] = wv.z; Ws[lk + 3][lr] = wv.w;
        __syncthreads();
#pragma unroll
        for (int kk = 0; kk < 16; kk++) {
            float4 a = *(const float4*)&As[kk][ty * 4];
            float4 b = *(const float4*)&Ws[kk][tx * 4];
            float ar[4] = {a.x, a.y, a.z, a.w};
            float br[4] = {b.x, b.y, b.z, b.w};
#pragma unroll
            for (int i = 0; i < 4; i++)
#pragma unroll
                for (int j = 0; j < 4; j++)
                    acc[i][j] = fmaf(ar[i], br[j], acc[i][j]);
        }
        __syncthreads();
    }
#pragma unroll
    for (int i = 0; i < 4; i++) {
        float4 o = make_float4(acc[i][0], acc[i][1], acc[i][2], acc[i][3]);
        *(float4*)&C[(size_t)(row0 + ty * 4 + i) * DM + col0 + tx * 4] = o;
    }
}

__global__ __launch_bounds__(256) void gemm_qkv(const float* __restrict__ q,
                                                const float* __restrict__ k,
                                                const float* __restrict__ v,
                                                const float* __restrict__ WQ,
                                                const float* __restrict__ WK,
                                                const float* __restrict__ WV) {
    const float* A;
    const float* W;
    float* C;
    if (blockIdx.z == 0)      { A = q; W = WQ; C = g_Q; }
    else if (blockIdx.z == 1) { A = k; W = WK; C = g_K; }
    else                      { A = v; W = WV; C = g_V; }
    gemm_body(A, W, C);
}

__global__ __launch_bounds__(256) void gemm_wo(const float* __restrict__ WO) {
    gemm_body(g_O, WO, g_Y);
}

// ---------------------------------------------------------------------------
// Flash attention: one block per (b, h, 64-query tile). 256 threads.
// SMEM: Qs (d-major), KP (K d-major, reused for P), Vs (natural). 48KB total.
// ---------------------------------------------------------------------------
__global__ __launch_bounds__(256) void attn_kernel(const int* __restrict__ mask) {
    __shared__ float Qs[64 * 64];  // Qs[d*64 + i]
    __shared__ float KP[64 * 64];  // K: [d*64 + j]   then   P: [i*64 + j]
    __shared__ float Vs[64 * 64];  // Vs[j*64 + d]

    const int tid = threadIdx.x;
    const int tx = tid & 15;
    const int ty = tid >> 4;
    const int b = blockIdx.z;
    const int h = blockIdx.y;
    const int n0 = blockIdx.x * 64;

    const int lr = tid >> 2;        // 0..63 (tile row)
    const int lc = (tid & 3) << 2;  // 0,4,8,12

    // Load Q tile transposed: Qs[d][i]
    const float* Qg = g_Q + ((size_t)(b * NN + n0 + lr)) * DM + h * HD;
#pragma unroll
    for (int p = 0; p < 4; p++) {
        const int d = lc + p * 16;
        float4 v = *(const float4*)(Qg + d);
        Qs[(d + 0) * 64 + lr] = v.x;
        Qs[(d + 1) * 64 + lr] = v.y;
        Qs[(d + 2) * 64 + lr] = v.z;
        Qs[(d + 3) * 64 + lr] = v.w;
    }

    float mrow[4], lrow[4], o[4][4];
#pragma unroll
    for (int i = 0; i < 4; i++) {
        mrow[i] = -1e30f;
        lrow[i] = 0.f;
#pragma unroll
        for (int j = 0; j < 4; j++) o[i][j] = 0.f;
    }
    const float scale = 0.125f;  // 1/sqrt(64)

    for (int m0 = 0; m0 < MM; m0 += 64) {
        __syncthreads();  // prior iteration done with KP/Vs; also covers Qs on iter 0

        // Load K tile transposed [d][j] and V tile natural [j][d]
        const float* Kg = g_K + ((size_t)(b * MM + m0 + lr)) * DM + h * HD;
        const float* Vg = g_V + ((size_t)(b * MM + m0 + lr)) * DM + h * HD;
#pragma unroll
        for (int p = 0; p < 4; p++) {
            const int d = lc + p * 16;
            float4 kv = *(const float4*)(Kg + d);
            KP[(d + 0) * 64 + lr] = kv.x;
            KP[(d + 1) * 64 + lr] = kv.y;
            KP[(d + 2) * 64 + lr] = kv.z;
            KP[(d + 3) * 64 + lr] = kv.w;
            float4 vv = *(const float4*)(Vg + d);
            *(float4*)&Vs[lr * 64 + d] = vv;
        }
        __syncthreads();

        // S = Q @ K^T   (4x4 microtile per thread)
        float s[4][4];
#pragma unroll
        for (int i = 0; i < 4; i++)
#pragma unroll
            for (int j = 0; j < 4; j++) s[i][j] = 0.f;
#pragma unroll 8
        for (int d = 0; d < 64; d++) {
            float4 a = *(const float4*)&Qs[d * 64 + ty * 4];
            float4 bb = *(const float4*)&KP[d * 64 + tx * 4];
            float ar[4] = {a.x, a.y, a.z, a.w};
            float br[4] = {bb.x, bb.y, bb.z, bb.w};
#pragma unroll
            for (int i = 0; i < 4; i++)
#pragma unroll
                for (int j = 0; j < 4; j++)
                    s[i][j] = fmaf(ar[i], br[j], s[i][j]);
        }

        // mask + scale
#pragma unroll
        for (int i = 0; i < 4; i++) {
            const int4 mk = *(const int4*)&mask[((size_t)(b * NN + n0 + ty * 4 + i)) * MM + m0 + tx * 4];
            s[i][0] = mk.x ? s[i][0] * scale : -1e30f;
            s[i][1] = mk.y ? s[i][1] * scale : -1e30f;
            s[i][2] = mk.z ? s[i][2] * scale : -1e30f;
            s[i][3] = mk.w ? s[i][3] * scale : -1e30f;
        }

        // Online softmax per row (reduce over the 16 tx lanes, width-16 shfl)
        float corr[4];
#pragma unroll
        for (int i = 0; i < 4; i++) {
            float v = fmaxf(fmaxf(s[i][0], s[i][1]), fmaxf(s[i][2], s[i][3]));
            v = fmaxf(v, __shfl_xor_sync(0xffffffffu, v, 1, 16));
            v = fmaxf(v, __shfl_xor_sync(0xffffffffu, v, 2, 16));
            v = fmaxf(v, __shfl_xor_sync(0xffffffffu, v, 4, 16));
            v = fmaxf(v, __shfl_xor_sync(0xffffffffu, v, 8, 16));
            const float mn = fmaxf(mrow[i], v);
            corr[i] = __expf(mrow[i] - mn);
            mrow[i] = mn;
            float ps = 0.f;
#pragma unroll
            for (int j = 0; j < 4; j++) {
                s[i][j] = __expf(s[i][j] - mn);
                ps += s[i][j];
            }
            ps += __shfl_xor_sync(0xffffffffu, ps, 1, 16);
            ps += __shfl_xor_sync(0xffffffffu, ps, 2, 16);
            ps += __shfl_xor_sync(0xffffffffu, ps, 4, 16);
            ps += __shfl_xor_sync(0xffffffffu, ps, 8, 16);
            lrow[i] = lrow[i] * corr[i] + ps;
        }

        __syncthreads();  // everyone done reading K from KP

        // Store P into KP (now [i][j])
#pragma unroll
        for (int i = 0; i < 4; i++) {
            float4 pv = make_float4(s[i][0], s[i][1], s[i][2], s[i][3]);
            *(float4*)&KP[(ty * 4 + i) * 64 + tx * 4] = pv;
        }
        __syncthreads();

        // O = O*corr + P @ V
#pragma unroll
        for (int i = 0; i < 4; i++)
#pragma unroll
            for (int dd = 0; dd < 4; dd++) o[i][dd] *= corr[i];

#pragma unroll 8
        for (int j = 0; j < 64; j++) {
            float4 bb = *(const float4*)&Vs[j * 64 + tx * 4];
            float br[4] = {bb.x, bb.y, bb.z, bb.w};
            float pr[4];
#pragma unroll
            for (int i = 0; i < 4; i++) pr[i] = KP[(ty * 4 + i) * 64 + j];
#pragma unroll
            for (int i = 0; i < 4; i++)
#pragma unroll
                for (int dd = 0; dd < 4; dd++)
                    o[i][dd] = fmaf(pr[i], br[dd], o[i][dd]);
        }
    }

    // Epilogue: divide by l, write back in [B*N, 512] layout (head-concat)
#pragma unroll
    for (int i = 0; i < 4; i++) {
        const float inv = 1.f / lrow[i];
        float4 ov = make_float4(o[i][0] * inv, o[i][1] * inv, o[i][2] * inv, o[i][3] * inv);
        *(float4*)&g_O[((size_t)(b * NN + n0 + ty * 4 + i)) * DM + h * HD + tx * 4] = ov;
    }
}

// ---------------------------------------------------------------------------
// Fused bias + residual + LayerNorm: one block per row.
// ---------------------------------------------------------------------------
__global__ __launch_bounds__(128) void ln_kernel(const float* __restrict__ query,
                                                 const float* __restrict__ bO,
                                                 const float* __restrict__ gamma,
                                                 const float* __restrict__ beta,
                                                 float* __restrict__ out) {
    const int r = blockIdx.x;
    const int tid = threadIdx.x;
    float x[4];
    float s = 0.f, s2 = 0.f;
#pragma unroll
    for (int p = 0; p < 4; p++) {
        const int c = tid + p * 128;
        const float v = g_Y[(size_t)r * DM + c] + bO[c] + query[(size_t)r * DM + c];
        x[p] = v;
        s += v;
        s2 += v * v;
    }
#pragma unroll
    for (int off = 16; off; off >>= 1) {
        s += __shfl_xor_sync(0xffffffffu, s, off);
        s2 += __shfl_xor_sync(0xffffffffu, s2, off);
    }
    __shared__ float rs[4], rs2[4];
    if ((tid & 31) == 0) {
        rs[tid >> 5] = s;
        rs2[tid >> 5] = s2;
    }
    __syncthreads();
    s = rs[0] + rs[1] + rs[2] + rs[3];
    s2 = rs2[0] + rs2[1] + rs2[2] + rs2[3];
    const float mu = s * (1.f / 512.f);
    const float var = s2 * (1.f / 512.f) - mu * mu;
    const float rstd = rsqrtf(var + 1e-5f);
#pragma unroll
    for (int p = 0; p < 4; p++) {
        const int c = tid + p * 128;
        out[(size_t)r * DM + c] = (x[p] - mu) * rstd * gamma[c] + beta[c];
    }
}

// ---------------------------------------------------------------------------
extern "C" void kernel_launch(void* const* d_in, const int* in_sizes, int n_in,
                              void* d_out, int out_size) {
    const float* query = (const float*)d_in[0];
    const float* key   = (const float*)d_in[1];
    const float* value = (const float*)d_in[2];
    const int*   mask  = (const int*)d_in[3];
    const float* WQ    = (const float*)d_in[4];
    const float* WK    = (const float*)d_in[5];
    const float* WV    = (const float*)d_in[6];
    const float* WO    = (const float*)d_in[7];
    const float* bO    = (const float*)d_in[8];
    const float* gamma = (const float*)d_in[9];
    const float* beta  = (const float*)d_in[10];
    float* out = (float*)d_out;

    dim3 g1(BB * NN / 64, DM / 64, 3);
    gemm_qkv<<<g1, 256>>>(query, key, value, WQ, WK, WV);

    dim3 ga(NN / 64, HH, BB);
    attn_kernel<<<ga, 256>>>(mask);

    dim3 g2(BB * NN / 64, DM / 64, 1);
    gemm_wo<<<g2, 256>>>(WO);

    ln_kernel<<<BB * NN, 128>>>(query, bO, gamma, beta, out);
}

// round 2
// speedup vs baseline: 1.8234x; 1.8234x over previous
#include <cuda_runtime.h>
#include <math.h>
#include <stdint.h>

#define BB 4
#define NN 2048
#define MM 2048
#define DM 512
#define HH 8
#define HD 64

// Scratch (allocation-free rule: __device__ globals)
__device__ float g_Q[BB * NN * DM];
__device__ float g_K[BB * MM * DM];
__device__ float g_V[BB * MM * DM];
__device__ float g_O[BB * NN * DM];
__device__ float g_Y[BB * NN * DM];

__device__ __forceinline__ uint32_t f2tf32(float x) {
    uint32_t r;
    asm("cvt.rna.tf32.f32 %0, %1;" : "=r"(r) : "f"(x));
    return r;
}

#define MMA_TF32(d, a0, a1, a2, a3, b0, b1)                                  \
    asm volatile(                                                            \
        "mma.sync.aligned.m16n8k8.row.col.f32.tf32.tf32.f32 "                \
        "{%0,%1,%2,%3},{%4,%5,%6,%7},{%8,%9},{%0,%1,%2,%3};"                 \
        : "+f"(d[0]), "+f"(d[1]), "+f"(d[2]), "+f"(d[3])                     \
        : "r"(a0), "r"(a1), "r"(a2), "r"(a3), "r"(b0), "r"(b1))

// ---------------------------------------------------------------------------
// Tensor-core GEMM: C[R][512] = A[R][512] @ W[512][512]^T   (tf32, fp32 accum)
// Block tile 128x64, 8 warps (4x2), warp tile 32x32, k-step 32.
// ---------------------------------------------------------------------------
__device__ __forceinline__ void gemm_body_tc(const float* __restrict__ A,
                                             const float* __restrict__ W,
                                             float* __restrict__ C) {
    __shared__ float As[128][36];
    __shared__ float Ws[64][36];
    const int tid = threadIdx.x;
    const int wid = tid >> 5;
    const int lane = tid & 31;
    const int g = lane >> 2;
    const int q = lane & 3;
    const int wm = (wid & 3) * 32;
    const int wn = (wid >> 2) * 32;
    const int row0 = blockIdx.x * 128;
    const int col0 = blockIdx.y * 64;

    float acc[2][4][4];
#pragma unroll
    for (int i = 0; i < 2; i++)
#pragma unroll
        for (int j = 0; j < 4; j++)
#pragma unroll
            for (int e = 0; e < 4; e++) acc[i][j][e] = 0.f;

    for (int k0 = 0; k0 < DM; k0 += 32) {
        __syncthreads();
        // Stage A tile 128x32
#pragma unroll
        for (int p = 0; p < 4; p++) {
            const int id = tid + 256 * p;
            const int r = id >> 3;
            const int c = (id & 7) * 4;
            float4 v = *(const float4*)&A[(size_t)(row0 + r) * DM + k0 + c];
            As[r][c + 0] = __uint_as_float(f2tf32(v.x));
            As[r][c + 1] = __uint_as_float(f2tf32(v.y));
            As[r][c + 2] = __uint_as_float(f2tf32(v.z));
            As[r][c + 3] = __uint_as_float(f2tf32(v.w));
        }
        // Stage W tile 64x32
#pragma unroll
        for (int p = 0; p < 2; p++) {
            const int id = tid + 256 * p;
            const int r = id >> 3;
            const int c = (id & 7) * 4;
            float4 v = *(const float4*)&W[(size_t)(col0 + r) * DM + k0 + c];
            Ws[r][c + 0] = __uint_as_float(f2tf32(v.x));
            Ws[r][c + 1] = __uint_as_float(f2tf32(v.y));
            Ws[r][c + 2] = __uint_as_float(f2tf32(v.z));
            Ws[r][c + 3] = __uint_as_float(f2tf32(v.w));
        }
        __syncthreads();

#pragma unroll
        for (int ks = 0; ks < 4; ks++) {
            const int k = ks * 8;
            uint32_t a[2][4];
#pragma unroll
            for (int im = 0; im < 2; im++) {
                const int r = wm + im * 16;
                a[im][0] = __float_as_uint(As[r + g][k + q]);
                a[im][1] = __float_as_uint(As[r + g + 8][k + q]);
                a[im][2] = __float_as_uint(As[r + g][k + q + 4]);
                a[im][3] = __float_as_uint(As[r + g + 8][k + q + 4]);
            }
#pragma unroll
            for (int jn = 0; jn < 4; jn++) {
                const int cc = wn + jn * 8;
                uint32_t b0 = __float_as_uint(Ws[cc + g][k + q]);
                uint32_t b1 = __float_as_uint(Ws[cc + g][k + q + 4]);
                MMA_TF32(acc[0][jn], a[0][0], a[0][1], a[0][2], a[0][3], b0, b1);
                MMA_TF32(acc[1][jn], a[1][0], a[1][1], a[1][2], a[1][3], b0, b1);
            }
        }
    }

#pragma unroll
    for (int im = 0; im < 2; im++) {
#pragma unroll
        for (int jn = 0; jn < 4; jn++) {
            const int r = row0 + wm + im * 16 + g;
            const int c = col0 + wn + jn * 8 + 2 * q;
            *(float2*)&C[(size_t)r * DM + c] = make_float2(acc[im][jn][0], acc[im][jn][1]);
            *(float2*)&C[(size_t)(r + 8) * DM + c] = make_float2(acc[im][jn][2], acc[im][jn][3]);
        }
    }
}

__global__ __launch_bounds__(256) void gemm_qkv(const float* __restrict__ q,
                                                const float* __restrict__ k,
                                                const float* __restrict__ v,
                                                const float* __restrict__ WQ,
                                                const float* __restrict__ WK,
                                                const float* __restrict__ WV) {
    const float* A;
    const float* W;
    float* C;
    if (blockIdx.z == 0)      { A = q; W = WQ; C = g_Q; }
    else if (blockIdx.z == 1) { A = k; W = WK; C = g_K; }
    else                      { A = v; W = WV; C = g_V; }
    gemm_body_tc(A, W, C);
}

__global__ __launch_bounds__(256) void gemm_wo(const float* __restrict__ WO) {
    gemm_body_tc(g_O, WO, g_Y);
}

// ---------------------------------------------------------------------------
// Tensor-core flash attention: block = (b, h, 64 query rows), 4 warps.
// Q fragments persistent in registers; K/V staged in SMEM (stride-72 pad).
// ---------------------------------------------------------------------------
#define KVS 72
__global__ __launch_bounds__(128) void attn_tc(const int* __restrict__ mask) {
    __shared__ float Ks[64 * KVS];
    __shared__ float Vs[64 * KVS];

    const int tid = threadIdx.x;
    const int w = tid >> 5;
    const int lane = tid & 31;
    const int g = lane >> 2;
    const int q = lane & 3;
    const int b = blockIdx.z;
    const int h = blockIdx.y;
    const int n0 = blockIdx.x * 64;

    // ---- Stage Q tile (64x64) into Ks, build persistent A-fragments ----
    {
        const float* Qg = g_Q + ((size_t)(b * NN + n0)) * DM + h * HD;
#pragma unroll
        for (int p = 0; p < 8; p++) {
            const int id = tid + 128 * p;
            const int r = id >> 4;
            const int c = (id & 15) * 4;
            float4 v = *(const float4*)&Qg[(size_t)r * DM + c];
            float* dst = &Ks[r * KVS + c];
            dst[0] = __uint_as_float(f2tf32(v.x));
            dst[1] = __uint_as_float(f2tf32(v.y));
            dst[2] = __uint_as_float(f2tf32(v.z));
            dst[3] = __uint_as_float(f2tf32(v.w));
        }
    }
    __syncthreads();
    uint32_t qa[8][4];
#pragma unroll
    for (int k8 = 0; k8 < 8; k8++) {
        const int r = 16 * w;
        const int k = 8 * k8;
        qa[k8][0] = __float_as_uint(Ks[(r + g) * KVS + k + q]);
        qa[k8][1] = __float_as_uint(Ks[(r + g + 8) * KVS + k + q]);
        qa[k8][2] = __float_as_uint(Ks[(r + g) * KVS + k + q + 4]);
        qa[k8][3] = __float_as_uint(Ks[(r + g + 8) * KVS + k + q + 4]);
    }

    float o[8][4];
#pragma unroll
    for (int d8 = 0; d8 < 8; d8++)
#pragma unroll
        for (int e = 0; e < 4; e++) o[d8][e] = 0.f;
    float m0r = -1e30f, m1r = -1e30f, l0 = 0.f, l1 = 0.f;
    const float scale = 0.125f;

    const int row_g = n0 + 16 * w + g;  // absolute query row (and +8)
    const int srcA = (lane & 28) | (q >> 1);
    const int srcB = srcA + 2;
    const bool odd = q & 1;

    for (int m0 = 0; m0 < MM; m0 += 64) {
        __syncthreads();
        // Stage K and V tiles (64x64 each)
        const float* Kg = g_K + ((size_t)(b * MM + m0)) * DM + h * HD;
        const float* Vg = g_V + ((size_t)(b * MM + m0)) * DM + h * HD;
#pragma unroll
        for (int p = 0; p < 8; p++) {
            const int id = tid + 128 * p;
            const int r = id >> 4;
            const int c = (id & 15) * 4;
            float4 kv = *(const float4*)&Kg[(size_t)r * DM + c];
            float* kd = &Ks[r * KVS + c];
            kd[0] = __uint_as_float(f2tf32(kv.x));
            kd[1] = __uint_as_float(f2tf32(kv.y));
            kd[2] = __uint_as_float(f2tf32(kv.z));
            kd[3] = __uint_as_float(f2tf32(kv.w));
            float4 vv = *(const float4*)&Vg[(size_t)r * DM + c];
            float* vd = &Vs[r * KVS + c];
            vd[0] = __uint_as_float(f2tf32(vv.x));
            vd[1] = __uint_as_float(f2tf32(vv.y));
            vd[2] = __uint_as_float(f2tf32(vv.z));
            vd[3] = __uint_as_float(f2tf32(vv.w));
        }
        __syncthreads();

        // ---- S = Q @ K^T ----
        float s[8][4];
#pragma unroll
        for (int j8 = 0; j8 < 8; j8++) {
#pragma unroll
            for (int e = 0; e < 4; e++) s[j8][e] = 0.f;
#pragma unroll
            for (int k8 = 0; k8 < 8; k8++) {
                const int k = 8 * k8;
                uint32_t b0 = __float_as_uint(Ks[(8 * j8 + g) * KVS + k + q]);
                uint32_t b1 = __float_as_uint(Ks[(8 * j8 + g) * KVS + k + q + 4]);
                MMA_TF32(s[j8], qa[k8][0], qa[k8][1], qa[k8][2], qa[k8][3], b0, b1);
            }
        }

        // ---- mask + scale ----
#pragma unroll
        for (int j8 = 0; j8 < 8; j8++) {
            const size_t col = (size_t)m0 + 8 * j8 + 2 * q;
            const int2 mk0 = *(const int2*)&mask[((size_t)b * NN + row_g) * MM + col];
            const int2 mk1 = *(const int2*)&mask[((size_t)b * NN + row_g + 8) * MM + col];
            s[j8][0] = mk0.x ? s[j8][0] * scale : -1e30f;
            s[j8][1] = mk0.y ? s[j8][1] * scale : -1e30f;
            s[j8][2] = mk1.x ? s[j8][2] * scale : -1e30f;
            s[j8][3] = mk1.y ? s[j8][3] * scale : -1e30f;
        }

        // ---- online softmax (rows g and g+8) ----
        float mx0 = -1e30f, mx1 = -1e30f;
#pragma unroll
        for (int j8 = 0; j8 < 8; j8++) {
            mx0 = fmaxf(mx0, fmaxf(s[j8][0], s[j8][1]));
            mx1 = fmaxf(mx1, fmaxf(s[j8][2], s[j8][3]));
        }
        mx0 = fmaxf(mx0, __shfl_xor_sync(0xffffffffu, mx0, 1));
        mx0 = fmaxf(mx0, __shfl_xor_sync(0xffffffffu, mx0, 2));
        mx1 = fmaxf(mx1, __shfl_xor_sync(0xffffffffu, mx1, 1));
        mx1 = fmaxf(mx1, __shfl_xor_sync(0xffffffffu, mx1, 2));
        const float mn0 = fmaxf(m0r, mx0);
        const float mn1 = fmaxf(m1r, mx1);
        const float corr0 = __expf(m0r - mn0);
        const float corr1 = __expf(m1r - mn1);
        m0r = mn0;
        m1r = mn1;
        float sum0 = 0.f, sum1 = 0.f;
#pragma unroll
        for (int j8 = 0; j8 < 8; j8++) {
            s[j8][0] = __expf(s[j8][0] - mn0);
            s[j8][1] = __expf(s[j8][1] - mn0);
            s[j8][2] = __expf(s[j8][2] - mn1);
            s[j8][3] = __expf(s[j8][3] - mn1);
            sum0 += s[j8][0] + s[j8][1];
            sum1 += s[j8][2] + s[j8][3];
        }
        sum0 += __shfl_xor_sync(0xffffffffu, sum0, 1);
        sum0 += __shfl_xor_sync(0xffffffffu, sum0, 2);
        sum1 += __shfl_xor_sync(0xffffffffu, sum1, 1);
        sum1 += __shfl_xor_sync(0xffffffffu, sum1, 2);
        l0 = l0 * corr0 + sum0;
        l1 = l1 * corr1 + sum1;

        // ---- convert P C-fragments -> A-fragments (in-warp shuffles) ----
#pragma unroll
        for (int j8 = 0; j8 < 8; j8++) {
            uint32_t c0 = f2tf32(s[j8][0]);
            uint32_t c1 = f2tf32(s[j8][1]);
            uint32_t c2 = f2tf32(s[j8][2]);
            uint32_t c3 = f2tf32(s[j8][3]);
            uint32_t u0 = __shfl_sync(0xffffffffu, c0, srcA);
            uint32_t u1 = __shfl_sync(0xffffffffu, c1, srcA);
            uint32_t u2 = __shfl_sync(0xffffffffu, c0, srcB);
            uint32_t u3 = __shfl_sync(0xffffffffu, c1, srcB);
            uint32_t u4 = __shfl_sync(0xffffffffu, c2, srcA);
            uint32_t u5 = __shfl_sync(0xffffffffu, c3, srcA);
            uint32_t u6 = __shfl_sync(0xffffffffu, c2, srcB);
            uint32_t u7 = __shfl_sync(0xffffffffu, c3, srcB);
            s[j8][0] = __uint_as_float(odd ? u1 : u0);  // a0: row g,   col q
            s[j8][1] = __uint_as_float(odd ? u5 : u4);  // a1: row g+8, col q
            s[j8][2] = __uint_as_float(odd ? u3 : u2);  // a2: row g,   col q+4
            s[j8][3] = __uint_as_float(odd ? u7 : u6);  // a3: row g+8, col q+4
        }

        // ---- rescale O, then O += P @ V ----
#pragma unroll
        for (int d8 = 0; d8 < 8; d8++) {
            o[d8][0] *= corr0;
            o[d8][1] *= corr0;
            o[d8][2] *= corr1;
            o[d8][3] *= corr1;
        }
#pragma unroll
        for (int d8 = 0; d8 < 8; d8++) {
#pragma unroll
            for (int k8 = 0; k8 < 8; k8++) {
                uint32_t b0 = __float_as_uint(Vs[(8 * k8 + q) * KVS + 8 * d8 + g]);
                uint32_t b1 = __float_as_uint(Vs[(8 * k8 + 4 + q) * KVS + 8 * d8 + g]);
                MMA_TF32(o[d8], __float_as_uint(s[k8][0]), __float_as_uint(s[k8][1]),
                         __float_as_uint(s[k8][2]), __float_as_uint(s[k8][3]), b0, b1);
            }
        }
    }

    // ---- epilogue ----
    const float inv0 = 1.f / l0;
    const float inv1 = 1.f / l1;
    float* Og = g_O + ((size_t)(b * NN + n0 + 16 * w)) * DM + h * HD;
#pragma unroll
    for (int d8 = 0; d8 < 8; d8++) {
        const int c = 8 * d8 + 2 * q;
        *(float2*)&Og[(size_t)g * DM + c] = make_float2(o[d8][0] * inv0, o[d8][1] * inv0);
        *(float2*)&Og[(size_t)(g + 8) * DM + c] = make_float2(o[d8][2] * inv1, o[d8][3] * inv1);
    }
}

// ---------------------------------------------------------------------------
// Fused bias + residual + LayerNorm: one block per row.
// ---------------------------------------------------------------------------
__global__ __launch_bounds__(128) void ln_kernel(const float* __restrict__ query,
                                                 const float* __restrict__ bO,
                                                 const float* __restrict__ gamma,
                                                 const float* __restrict__ beta,
                                                 float* __restrict__ out) {
    const int r = blockIdx.x;
    const int tid = threadIdx.x;
    float x[4];
    float s = 0.f, s2 = 0.f;
#pragma unroll
    for (int p = 0; p < 4; p++) {
        const int c = tid + p * 128;
        const float v = g_Y[(size_t)r * DM + c] + bO[c] + query[(size_t)r * DM + c];
        x[p] = v;
        s += v;
        s2 += v * v;
    }
#pragma unroll
    for (int off = 16; off; off >>= 1) {
        s += __shfl_xor_sync(0xffffffffu, s, off);
        s2 += __shfl_xor_sync(0xffffffffu, s2, off);
    }
    __shared__ float rs[4], rs2[4];
    if ((tid & 31) == 0) {
        rs[tid >> 5] = s;
        rs2[tid >> 5] = s2;
    }
    __syncthreads();
    s = rs[0] + rs[1] + rs[2] + rs[3];
    s2 = rs2[0] + rs2[1] + rs2[2] + rs2[3];
    const float mu = s * (1.f / 512.f);
    const float var = s2 * (1.f / 512.f) - mu * mu;
    const float rstd = rsqrtf(var + 1e-5f);
#pragma unroll
    for (int p = 0; p < 4; p++) {
        const int c = tid + p * 128;
        out[(size_t)r * DM + c] = (x[p] - mu) * rstd * gamma[c] + beta[c];
    }
}

// ---------------------------------------------------------------------------
extern "C" void kernel_launch(void* const* d_in, const int* in_sizes, int n_in,
                              void* d_out, int out_size) {
    const float* query = (const float*)d_in[0];
    const float* key   = (const float*)d_in[1];
    const float* value = (const float*)d_in[2];
    const int*   mask  = (const int*)d_in[3];
    const float* WQ    = (const float*)d_in[4];
    const float* WK    = (const float*)d_in[5];
    const float* WV    = (const float*)d_in[6];
    const float* WO    = (const float*)d_in[7];
    const float* bO    = (const float*)d_in[8];
    const float* gamma = (const float*)d_in[9];
    const float* beta  = (const float*)d_in[10];
    float* out = (float*)d_out;

    dim3 g1(BB * NN / 128, DM / 64, 3);
    gemm_qkv<<<g1, 256>>>(query, key, value, WQ, WK, WV);

    dim3 ga(NN / 64, HH, BB);
    attn_tc<<<ga, 128>>>(mask);

    dim3 g2(BB * NN / 128, DM / 64, 1);
    gemm_wo<<<g2, 256>>>(WO);

    ln_kernel<<<BB * NN, 128>>>(query, bO, gamma, beta, out);
}

// round 3
// speedup vs baseline: 4.3067x; 2.3619x over previous
#include <cuda_runtime.h>
#include <cuda_fp16.h>
#include <math.h>
#include <stdint.h>

#define BB 4
#define NN 2048
#define MM 2048
#define DM 512
#define HH 8
#define HD 64

// fp16 intermediates (halve staging traffic); LN input stays fp32
__device__ __half g_Q[BB * NN * DM];
__device__ __half g_K[BB * MM * DM];
__device__ __half g_V[BB * MM * DM];
__device__ __half g_O[BB * NN * DM];
__device__ float  g_Y[BB * NN * DM];

__device__ __forceinline__ uint32_t pack_h2(float a, float b) {
    __half2 h = __floats2half2_rn(a, b);
    return *reinterpret_cast<uint32_t*>(&h);
}

__device__ __forceinline__ uint32_t smem_u32(const void* p) {
    return (uint32_t)__cvta_generic_to_shared(p);
}

#define LDSM_X4(d0, d1, d2, d3, addr)                                         \
    asm volatile("ldmatrix.sync.aligned.m8n8.x4.shared.b16 {%0,%1,%2,%3},[%4];" \
                 : "=r"(d0), "=r"(d1), "=r"(d2), "=r"(d3) : "r"(addr))

#define LDSM_X4_T(d0, d1, d2, d3, addr)                                       \
    asm volatile("ldmatrix.sync.aligned.m8n8.x4.trans.shared.b16 {%0,%1,%2,%3},[%4];" \
                 : "=r"(d0), "=r"(d1), "=r"(d2), "=r"(d3) : "r"(addr))

#define MMA_F16(d, a0, a1, a2, a3, b0, b1)                                    \
    asm volatile(                                                             \
        "mma.sync.aligned.m16n8k16.row.col.f32.f16.f16.f32 "                  \
        "{%0,%1,%2,%3},{%4,%5,%6,%7},{%8,%9},{%0,%1,%2,%3};"                  \
        : "+f"(d[0]), "+f"(d[1]), "+f"(d[2]), "+f"(d[3])                      \
        : "r"(a0), "r"(a1), "r"(a2), "r"(a3), "r"(b0), "r"(b1))

// ---------------------------------------------------------------------------
// fp16 tensor-core GEMM: C[R][512] = A[R][512] @ W[512][512]^T
// Block 128x64, 8 warps (4x2), warp tile 32x32, k-step 32, ldmatrix feeds.
// ---------------------------------------------------------------------------
#define GS 40  // smem row stride (halves): 80B = 5*16B, conflict-free LDSM

template <bool A_HALF, bool OUT_HALF>
__device__ __forceinline__ void gemm_body_f16(const void* __restrict__ Ain,
                                              const float* __restrict__ W,
                                              void* __restrict__ Cout) {
    __shared__ __align__(16) __half As[128 * GS];
    __shared__ __align__(16) __half Ws[64 * GS];
    const int tid = threadIdx.x;
    const int wid = tid >> 5;
    const int lane = tid & 31;
    const int g = lane >> 2;
    const int q = lane & 3;
    const int wm = (wid & 3) * 32;
    const int wn = (wid >> 2) * 32;
    const int row0 = blockIdx.x * 128;
    const int col0 = blockIdx.y * 64;

    const int a_row = (lane & 7) + ((lane >> 3) & 1) * 8;
    const int a_col = ((lane >> 4) & 1) * 8;
    const int b_row = ((lane >> 4) & 1) * 8 + (lane & 7);
    const int b_col = ((lane >> 3) & 1) * 8;

    const uint32_t as_base = smem_u32(As);
    const uint32_t ws_base = smem_u32(Ws);

    float acc[2][4][4];
#pragma unroll
    for (int i = 0; i < 2; i++)
#pragma unroll
        for (int j = 0; j < 4; j++)
#pragma unroll
            for (int e = 0; e < 4; e++) acc[i][j][e] = 0.f;

    for (int k0 = 0; k0 < DM; k0 += 32) {
        __syncthreads();
        // Stage A 128x32
        if (A_HALF) {
            const __half* A = (const __half*)Ain;
#pragma unroll
            for (int p = 0; p < 4; p++) {
                const int id = tid + 256 * p;
                const int r = id >> 3;
                const int c = (id & 7) * 4;
                *(uint2*)&As[r * GS + c] =
                    *(const uint2*)&A[(size_t)(row0 + r) * DM + k0 + c];
            }
        } else {
            const float* A = (const float*)Ain;
#pragma unroll
            for (int p = 0; p < 4; p++) {
                const int id = tid + 256 * p;
                const int r = id >> 3;
                const int c = (id & 7) * 4;
                float4 v = *(const float4*)&A[(size_t)(row0 + r) * DM + k0 + c];
                uint2 h;
                h.x = pack_h2(v.x, v.y);
                h.y = pack_h2(v.z, v.w);
                *(uint2*)&As[r * GS + c] = h;
            }
        }
        // Stage W 64x32
#pragma unroll
        for (int p = 0; p < 2; p++) {
            const int id = tid + 256 * p;
            const int r = id >> 3;
            const int c = (id & 7) * 4;
            float4 v = *(const float4*)&W[(size_t)(col0 + r) * DM + k0 + c];
            uint2 h;
            h.x = pack_h2(v.x, v.y);
            h.y = pack_h2(v.z, v.w);
            *(uint2*)&Ws[r * GS + c] = h;
        }
        __syncthreads();

#pragma unroll
        for (int kk = 0; kk < 2; kk++) {
            uint32_t a[2][4];
#pragma unroll
            for (int im = 0; im < 2; im++) {
                const uint32_t addr = as_base +
                    ((wm + 16 * im + a_row) * GS + 16 * kk + a_col) * 2;
                LDSM_X4(a[im][0], a[im][1], a[im][2], a[im][3], addr);
            }
#pragma unroll
            for (int jp = 0; jp < 2; jp++) {
                uint32_t b0, b1, b2, b3;
                const uint32_t addr = ws_base +
                    ((wn + 16 * jp + b_row) * GS + 16 * kk + b_col) * 2;
                LDSM_X4(b0, b1, b2, b3, addr);
#pragma unroll
                for (int im = 0; im < 2; im++) {
                    MMA_F16(acc[im][2 * jp], a[im][0], a[im][1], a[im][2], a[im][3], b0, b1);
                    MMA_F16(acc[im][2 * jp + 1], a[im][0], a[im][1], a[im][2], a[im][3], b2, b3);
                }
            }
        }
    }

#pragma unroll
    for (int im = 0; im < 2; im++) {
#pragma unroll
        for (int jn = 0; jn < 4; jn++) {
            const int r = row0 + wm + im * 16 + g;
            const int c = col0 + wn + jn * 8 + 2 * q;
            if (OUT_HALF) {
                __half* C = (__half*)Cout;
                *(uint32_t*)&C[(size_t)r * DM + c] = pack_h2(acc[im][jn][0], acc[im][jn][1]);
                *(uint32_t*)&C[(size_t)(r + 8) * DM + c] = pack_h2(acc[im][jn][2], acc[im][jn][3]);
            } else {
                float* C = (float*)Cout;
                *(float2*)&C[(size_t)r * DM + c] = make_float2(acc[im][jn][0], acc[im][jn][1]);
                *(float2*)&C[(size_t)(r + 8) * DM + c] = make_float2(acc[im][jn][2], acc[im][jn][3]);
            }
        }
    }
}

__global__ __launch_bounds__(256) void gemm_qkv(const float* __restrict__ q,
                                                const float* __restrict__ k,
                                                const float* __restrict__ v,
                                                const float* __restrict__ WQ,
                                                const float* __restrict__ WK,
                                                const float* __restrict__ WV) {
    if (blockIdx.z == 0)      gemm_body_f16<false, true>(q, WQ, g_Q);
    else if (blockIdx.z == 1) gemm_body_f16<false, true>(k, WK, g_K);
    else                      gemm_body_f16<false, true>(v, WV, g_V);
}

__global__ __launch_bounds__(256) void gemm_wo(const float* __restrict__ WO) {
    gemm_body_f16<true, false>(g_O, WO, g_Y);
}

// ---------------------------------------------------------------------------
// fp16 tensor-core flash attention: block = (b, h, 64 query rows), 4 warps.
// Q fragments persist in registers; K row-major, V row-major + ldmatrix.trans.
// ---------------------------------------------------------------------------
#define KS 72  // 144B rows = 9*16B: LDSM-aligned, conflict-free

__global__ __launch_bounds__(128) void attn_tc(const int* __restrict__ mask) {
    __shared__ __align__(16) __half Ks[64 * KS];
    __shared__ __align__(16) __half Vs[64 * KS];

    const int tid = threadIdx.x;
    const int w = tid >> 5;
    const int lane = tid & 31;
    const int g = lane >> 2;
    const int q = lane & 3;
    const int b = blockIdx.z;
    const int h = blockIdx.y;
    const int n0 = blockIdx.x * 64;

    const int a_row = (lane & 7) + ((lane >> 3) & 1) * 8;
    const int a_col = ((lane >> 4) & 1) * 8;
    const int b_row = ((lane >> 4) & 1) * 8 + (lane & 7);
    const int b_col = ((lane >> 3) & 1) * 8;

    const uint32_t ks_base = smem_u32(Ks);
    const uint32_t vs_base = smem_u32(Vs);

    // ---- Stage Q (64x64 halves) into Ks, load persistent A-fragments ----
    {
        const __half* Qg = g_Q + ((size_t)(b * NN + n0)) * DM + h * HD;
#pragma unroll
        for (int p = 0; p < 4; p++) {
            const int id = tid + 128 * p;
            const int r = id >> 3;
            const int c = (id & 7) * 8;
            *(uint4*)&Ks[r * KS + c] = *(const uint4*)&Qg[(size_t)r * DM + c];
        }
    }
    __syncthreads();
    uint32_t qa[4][4];
#pragma unroll
    for (int kk = 0; kk < 4; kk++) {
        const uint32_t addr = ks_base + ((16 * w + a_row) * KS + 16 * kk + a_col) * 2;
        LDSM_X4(qa[kk][0], qa[kk][1], qa[kk][2], qa[kk][3], addr);
    }

    float o[8][4];
#pragma unroll
    for (int d8 = 0; d8 < 8; d8++)
#pragma unroll
        for (int e = 0; e < 4; e++) o[d8][e] = 0.f;
    float m0r = -1e30f, m1r = -1e30f, l0 = 0.f, l1 = 0.f;
    const float scale = 0.125f;
    const int row_g = n0 + 16 * w + g;

    for (int m0 = 0; m0 < MM; m0 += 64) {
        __syncthreads();
        // Stage K and V tiles (pure fp16 copies)
        const __half* Kg = g_K + ((size_t)(b * MM + m0)) * DM + h * HD;
        const __half* Vg = g_V + ((size_t)(b * MM + m0)) * DM + h * HD;
#pragma unroll
        for (int p = 0; p < 4; p++) {
            const int id = tid + 128 * p;
            const int r = id >> 3;
            const int c = (id & 7) * 8;
            *(uint4*)&Ks[r * KS + c] = *(const uint4*)&Kg[(size_t)r * DM + c];
            *(uint4*)&Vs[r * KS + c] = *(const uint4*)&Vg[(size_t)r * DM + c];
        }
        __syncthreads();

        // ---- S = Q @ K^T ----
        float s[8][4];
#pragma unroll
        for (int j8 = 0; j8 < 8; j8++)
#pragma unroll
            for (int e = 0; e < 4; e++) s[j8][e] = 0.f;
#pragma unroll
        for (int kk = 0; kk < 4; kk++) {
#pragma unroll
            for (int jp = 0; jp < 4; jp++) {
                uint32_t b0, b1, b2, b3;
                const uint32_t addr = ks_base + ((16 * jp + b_row) * KS + 16 * kk + b_col) * 2;
                LDSM_X4(b0, b1, b2, b3, addr);
                MMA_F16(s[2 * jp], qa[kk][0], qa[kk][1], qa[kk][2], qa[kk][3], b0, b1);
                MMA_F16(s[2 * jp + 1], qa[kk][0], qa[kk][1], qa[kk][2], qa[kk][3], b2, b3);
            }
        }

        // ---- mask + scale ----
#pragma unroll
        for (int j8 = 0; j8 < 8; j8++) {
            const size_t col = (size_t)m0 + 8 * j8 + 2 * q;
            const int2 mk0 = *(const int2*)&mask[((size_t)b * NN + row_g) * MM + col];
            const int2 mk1 = *(const int2*)&mask[((size_t)b * NN + row_g + 8) * MM + col];
            s[j8][0] = mk0.x ? s[j8][0] * scale : -1e30f;
            s[j8][1] = mk0.y ? s[j8][1] * scale : -1e30f;
            s[j8][2] = mk1.x ? s[j8][2] * scale : -1e30f;
            s[j8][3] = mk1.y ? s[j8][3] * scale : -1e30f;
        }

        // ---- online softmax (rows g and g+8) ----
        float mx0 = -1e30f, mx1 = -1e30f;
#pragma unroll
        for (int j8 = 0; j8 < 8; j8++) {
            mx0 = fmaxf(mx0, fmaxf(s[j8][0], s[j8][1]));
            mx1 = fmaxf(mx1, fmaxf(s[j8][2], s[j8][3]));
        }
        mx0 = fmaxf(mx0, __shfl_xor_sync(0xffffffffu, mx0, 1));
        mx0 = fmaxf(mx0, __shfl_xor_sync(0xffffffffu, mx0, 2));
        mx1 = fmaxf(mx1, __shfl_xor_sync(0xffffffffu, mx1, 1));
        mx1 = fmaxf(mx1, __shfl_xor_sync(0xffffffffu, mx1, 2));
        const float mn0 = fmaxf(m0r, mx0);
        const float mn1 = fmaxf(m1r, mx1);
        const float corr0 = __expf(m0r - mn0);
        const float corr1 = __expf(m1r - mn1);
        m0r = mn0;
        m1r = mn1;
        float sum0 = 0.f, sum1 = 0.f;
#pragma unroll
        for (int j8 = 0; j8 < 8; j8++) {
            s[j8][0] = __expf(s[j8][0] - mn0);
            s[j8][1] = __expf(s[j8][1] - mn0);
            s[j8][2] = __expf(s[j8][2] - mn1);
            s[j8][3] = __expf(s[j8][3] - mn1);
            sum0 += s[j8][0] + s[j8][1];
            sum1 += s[j8][2] + s[j8][3];
        }
        sum0 += __shfl_xor_sync(0xffffffffu, sum0, 1);
        sum0 += __shfl_xor_sync(0xffffffffu, sum0, 2);
        sum1 += __shfl_xor_sync(0xffffffffu, sum1, 1);
        sum1 += __shfl_xor_sync(0xffffffffu, sum1, 2);
        l0 = l0 * corr0 + sum0;
        l1 = l1 * corr1 + sum1;

        // ---- pack P C-frags -> fp16 A-frags (no shuffles needed!) ----
        uint32_t pa[4][4];
#pragma unroll
        for (int kk = 0; kk < 4; kk++) {
            pa[kk][0] = pack_h2(s[2 * kk][0], s[2 * kk][1]);
            pa[kk][1] = pack_h2(s[2 * kk][2], s[2 * kk][3]);
            pa[kk][2] = pack_h2(s[2 * kk + 1][0], s[2 * kk + 1][1]);
            pa[kk][3] = pack_h2(s[2 * kk + 1][2], s[2 * kk + 1][3]);
        }

        // ---- rescale O, then O += P @ V (V via ldmatrix.trans) ----
#pragma unroll
        for (int d8 = 0; d8 < 8; d8++) {
            o[d8][0] *= corr0;
            o[d8][1] *= corr0;
            o[d8][2] *= corr1;
            o[d8][3] *= corr1;
        }
#pragma unroll
        for (int dp = 0; dp < 4; dp++) {
#pragma unroll
            for (int kk = 0; kk < 4; kk++) {
                uint32_t t0, t1, t2, t3;
                const uint32_t addr = vs_base + ((16 * kk + a_row) * KS + 16 * dp + a_col) * 2;
                LDSM_X4_T(t0, t1, t2, t3, addr);
                MMA_F16(o[2 * dp], pa[kk][0], pa[kk][1], pa[kk][2], pa[kk][3], t0, t1);
                MMA_F16(o[2 * dp + 1], pa[kk][0], pa[kk][1], pa[kk][2], pa[kk][3], t2, t3);
            }
        }
    }

    // ---- epilogue: normalize and write fp16 ----
    const float inv0 = 1.f / l0;
    const float inv1 = 1.f / l1;
    __half* Og = g_O + ((size_t)(b * NN + n0 + 16 * w)) * DM + h * HD;
#pragma unroll
    for (int d8 = 0; d8 < 8; d8++) {
        const int c = 8 * d8 + 2 * q;
        *(uint32_t*)&Og[(size_t)g * DM + c] = pack_h2(o[d8][0] * inv0, o[d8][1] * inv0);
        *(uint32_t*)&Og[(size_t)(g + 8) * DM + c] = pack_h2(o[d8][2] * inv1, o[d8][3] * inv1);
    }
}

// ---------------------------------------------------------------------------
// Fused bias + residual + LayerNorm: one block per row.
// ---------------------------------------------------------------------------
__global__ __launch_bounds__(128) void ln_kernel(const float* __restrict__ query,
                                                 const float* __restrict__ bO,
                                                 const float* __restrict__ gamma,
                                                 const float* __restrict__ beta,
                                                 float* __restrict__ out) {
    const int r = blockIdx.x;
    const int tid = threadIdx.x;
    float x[4];
    float s = 0.f, s2 = 0.f;
#pragma unroll
    for (int p = 0; p < 4; p++) {
        const int c = tid + p * 128;
        const float v = g_Y[(size_t)r * DM + c] + bO[c] + query[(size_t)r * DM + c];
        x[p] = v;
        s += v;
        s2 += v * v;
    }
#pragma unroll
    for (int off = 16; off; off >>= 1) {
        s += __shfl_xor_sync(0xffffffffu, s, off);
        s2 += __shfl_xor_sync(0xffffffffu, s2, off);
    }
    __shared__ float rs[4], rs2[4];
    if ((tid & 31) == 0) {
        rs[tid >> 5] = s;
        rs2[tid >> 5] = s2;
    }
    __syncthreads();
    s = rs[0] + rs[1] + rs[2] + rs[3];
    s2 = rs2[0] + rs2[1] + rs2[2] + rs2[3];
    const float mu = s * (1.f / 512.f);
    const float var = s2 * (1.f / 512.f) - mu * mu;
    const float rstd = rsqrtf(var + 1e-5f);
#pragma unroll
    for (int p = 0; p < 4; p++) {
        const int c = tid + p * 128;
        out[(size_t)r * DM + c] = (x[p] - mu) * rstd * gamma[c] + beta[c];
    }
}

// ---------------------------------------------------------------------------
extern "C" void kernel_launch(void* const* d_in, const int* in_sizes, int n_in,
                              void* d_out, int out_size) {
    const float* query = (const float*)d_in[0];
    const float* key   = (const float*)d_in[1];
    const float* value = (const float*)d_in[2];
    const int*   mask  = (const int*)d_in[3];
    const float* WQ    = (const float*)d_in[4];
    const float* WK    = (const float*)d_in[5];
    const float* WV    = (const float*)d_in[6];
    const float* WO    = (const float*)d_in[7];
    const float* bO    = (const float*)d_in[8];
    const float* gamma = (const float*)d_in[9];
    const float* beta  = (const float*)d_in[10];
    float* out = (float*)d_out;

    dim3 g1(BB * NN / 128, DM / 64, 3);
    gemm_qkv<<<g1, 256>>>(query, key, value, WQ, WK, WV);

    dim3 ga(NN / 64, HH, BB);
    attn_tc<<<ga, 128>>>(mask);

    dim3 g2(BB * NN / 128, DM / 64, 1);
    gemm_wo<<<g2, 256>>>(WO);

    ln_kernel<<<BB * NN, 128>>>(query, bO, gamma, beta, out);
}